// round 4
// baseline (speedup 1.0000x reference)
#include <cuda_runtime.h>
#include <cstdint>
#include <cstdio>

#define DEV __device__ __forceinline__

namespace {

constexpr int LEADS = 12;
constexpr int FIN   = 512;
constexpr int HID   = 256;
constexpr int OUTF  = 128;
constexpr int TOTAL_B = 16384;
constexpr int TOTAL_ROWS = TOTAL_B * LEADS;   // 196608

constexpr int SAMP = 10;       // samples per CTA
constexpr int RT   = 128;      // padded row-tile (10*12=120 -> 128)
constexpr int KC   = 16;       // K chunk streamed through SMEM
constexpr int XSS  = 20;       // Xs row stride (floats): 20 % 8 == 4 -> conflict-free A frags
constexpr int WSS  = 264;      // Ws row stride: 264 % 32 == 8 -> conflict-free B frags
constexpr int HS   = 260;      // Hbuf row stride: 260 % 32 == 4 -> conflict-free A frags
constexpr int NTHREADS = 512;

constexpr int OFF_H = 0;
constexpr int SZ_H  = RT * HS;            // 33280 floats
constexpr int OFF_X = OFF_H + SZ_H;
constexpr int SZ_X  = 2 * RT * XSS;       // 5120
constexpr int OFF_W = OFF_X + SZ_X;
constexpr int SZ_W  = 2 * KC * WSS;       // 8448
constexpr int OFF_A = OFF_W + SZ_W;
constexpr int SMEM_FLOATS = OFF_A + 160;  // A matrix + pad
constexpr int SMEM_BYTES  = SMEM_FLOATS * 4;   // ~188 KB

DEV uint32_t f2tf(float f) {
  uint32_t u;
  asm("cvt.rna.tf32.f32 %0, %1;" : "=r"(u) : "f"(f));
  return u;
}
DEV float tfv(float f) { return __uint_as_float(f2tf(f)); }

DEV void mma8(float d[4], const uint32_t a[4], const uint32_t b[2]) {
  asm volatile(
    "mma.sync.aligned.m16n8k8.row.col.f32.tf32.tf32.f32 "
    "{%0,%1,%2,%3},{%4,%5,%6,%7},{%8,%9},{%0,%1,%2,%3};"
    : "+f"(d[0]), "+f"(d[1]), "+f"(d[2]), "+f"(d[3])
    : "r"(a[0]), "r"(a[1]), "r"(a[2]), "r"(a[3]), "r"(b[0]), "r"(b[1]));
}

// Warp-level GEMM over one K chunk of KC.
// As: warp's 32-row block base (row-major, stride astr, tf32 values)
// Bs: warp's col block base within Ws ([k][n], stride WSS, tf32 values)
template<int NT>
DEV void gemm_chunk(const float* __restrict__ As, int astr,
                    const float* __restrict__ Bs,
                    int lane, float acc[2][8][4]) {
  const int r = lane >> 2, c = lane & 3;
  #pragma unroll
  for (int k0 = 0; k0 < KC; k0 += 8) {
    uint32_t a[2][4];
    #pragma unroll
    for (int mi = 0; mi < 2; mi++) {
      const float* ap = As + (mi * 16 + r) * astr + k0 + c;
      a[mi][0] = __float_as_uint(ap[0]);
      a[mi][1] = __float_as_uint(ap[8 * astr]);
      a[mi][2] = __float_as_uint(ap[4]);
      a[mi][3] = __float_as_uint(ap[8 * astr + 4]);
    }
    #pragma unroll
    for (int nj = 0; nj < NT; nj++) {
      const float* bp = Bs + (k0 + c) * WSS + nj * 8 + r;
      uint32_t b[2];
      b[0] = __float_as_uint(bp[0]);
      b[1] = __float_as_uint(bp[4 * WSS]);
      mma8(acc[0][nj], a[0], b);
      mma8(acc[1][nj], a[1], b);
    }
  }
}

__global__ void __launch_bounds__(NTHREADS, 1)
ecg_fused_kernel(const float* __restrict__ x,
                 const float* __restrict__ W1, const float* __restrict__ b1,
                 const float* __restrict__ W2, const float* __restrict__ b2,
                 const float* __restrict__ W3, const float* __restrict__ b3,
                 float* __restrict__ out)
{
  extern __shared__ float sm[];
  float* Hb  = sm + OFF_H;
  float* Xs  = sm + OFF_X;
  float* Wsm = sm + OFF_W;
  float* Am  = sm + OFF_A;

  const int tid  = threadIdx.x;
  const int lane = tid & 31;
  const int wid  = tid >> 5;
  const int wm   = wid >> 2;   // 0..3 row block (32 rows each)
  const int wn   = wid & 3;    // 0..3 col block
  const int s0    = blockIdx.x * SAMP;
  const int nsamp = min(SAMP, TOTAL_B - s0);
  const int row0  = s0 * LEADS;

  // ---- Build normalized adjacency (matches reference _norm_adj) ----
  if (tid == 0) {
    const int ci[15] = {0,0,1,0,1,2,0,1,1,2,6,7,8,9,10};
    const int cj[15] = {1,2,2,3,3,3,4,4,5,5,7,8,9,10,11};
    float ae[12][12];
    for (int i = 0; i < 12; i++)
      for (int j = 0; j < 12; j++) ae[i][j] = 0.f;
    for (int p = 0; p < 15; p++) { ae[ci[p]][cj[p]] = 1.f; ae[cj[p]][ci[p]] = 1.f; }
    for (int i = 0; i < 12; i++) ae[i][i] = 2.f;
    float dinv[12];
    for (int i = 0; i < 12; i++) {
      float s = 0.f;
      for (int j = 0; j < 12; j++) s += ae[i][j];
      dinv[i] = (float)(1.0 / sqrt((double)s));
    }
    for (int i = 0; i < 12; i++)
      for (int j = 0; j < 12; j++)
        Am[i * 12 + j] = dinv[i] * ae[i][j] * dinv[j];
  }

  float acc[2][8][4];

  // Epilogue: store accumulators into Hbuf
  auto store_acc = [&](int wcols, int ntiles) {
    const int r = lane >> 2, c2 = (lane & 3) * 2;
    #pragma unroll
    for (int mi = 0; mi < 2; mi++)
      for (int nj = 0; nj < 8; nj++) {
        if (nj >= ntiles) break;
        int row = wm * 32 + mi * 16 + r;
        int col = wn * wcols + nj * 8 + c2;
        *reinterpret_cast<float2*>(Hb + row * HS + col) =
            make_float2(acc[mi][nj][0], acc[mi][nj][1]);
        *reinterpret_cast<float2*>(Hb + (row + 8) * HS + col) =
            make_float2(acc[mi][nj][2], acc[mi][nj][3]);
      }
  };

  // Lead-mix + bias + relu + tf32 requantize, in place in Hbuf
  auto mix_relu = [&](int ncolshift, const float* bias) {
    const int ncol  = 1 << ncolshift;
    const int ntask = nsamp * ncol;
    for (int t = tid; t < ntask; t += NTHREADS) {
      int s = t >> ncolshift, cc = t & (ncol - 1);
      float* base = Hb + (s * LEADS) * HS + cc;
      float v[12];
      #pragma unroll
      for (int l = 0; l < 12; l++) v[l] = base[l * HS];
      float bv = bias[cc];
      #pragma unroll
      for (int n = 0; n < 12; n++) {
        float h = bv;
        #pragma unroll
        for (int m = 0; m < 12; m++) h = fmaf(Am[n * 12 + m], v[m], h);
        h = fmaxf(h, 0.f);
        base[n * HS] = tfv(h);
      }
    }
  };

  // ======================= Layer 1: X(128x512) @ W1(512x256) =======================
  {
    #pragma unroll
    for (int mi = 0; mi < 2; mi++)
      for (int nj = 0; nj < 8; nj++)
        for (int q = 0; q < 4; q++) acc[mi][nj][q] = 0.f;

    const int xr = tid >> 2, xc4 = tid & 3;
    float4 px, pw[2];

    auto ldx = [&](int kb) {
      int gr = row0 + xr;
      if (gr < TOTAL_ROWS)
        px = *reinterpret_cast<const float4*>(x + (size_t)gr * FIN + kb + xc4 * 4);
      else
        px = make_float4(0.f, 0.f, 0.f, 0.f);
    };
    auto stx = [&](int buf) {
      float4 o;
      o.x = tfv(px.x); o.y = tfv(px.y); o.z = tfv(px.z); o.w = tfv(px.w);
      *reinterpret_cast<float4*>(Xs + buf * (RT * XSS) + xr * XSS + xc4 * 4) = o;
    };
    auto ldw = [&](int kb) {
      #pragma unroll
      for (int i = 0; i < 2; i++) {
        int idx = tid + i * NTHREADS;
        int k = idx >> 6, c4 = idx & 63;
        pw[i] = *reinterpret_cast<const float4*>(W1 + (size_t)(kb + k) * HID + c4 * 4);
      }
    };
    auto stw = [&](int buf) {
      #pragma unroll
      for (int i = 0; i < 2; i++) {
        int idx = tid + i * NTHREADS;
        int k = idx >> 6, c4 = idx & 63;
        float4 v = pw[i], o;
        o.x = tfv(v.x); o.y = tfv(v.y); o.z = tfv(v.z); o.w = tfv(v.w);
        *reinterpret_cast<float4*>(Wsm + buf * (KC * WSS) + k * WSS + c4 * 4) = o;
      }
    };

    ldx(0); ldw(0);
    stx(0); stw(0);
    __syncthreads();
    constexpr int NC = FIN / KC;   // 32 chunks
    for (int ck = 0; ck < NC; ck++) {
      if (ck + 1 < NC) { ldx((ck + 1) * KC); ldw((ck + 1) * KC); }
      const float* As = Xs + (ck & 1) * (RT * XSS) + (wm * 32) * XSS;
      const float* Bs = Wsm + (ck & 1) * (KC * WSS) + wn * 64;
      gemm_chunk<8>(As, XSS, Bs, lane, acc);
      if (ck + 1 < NC) { stx((ck + 1) & 1); stw((ck + 1) & 1); }
      __syncthreads();
    }
    store_acc(64, 8);
    __syncthreads();
    mix_relu(8, b1);
    __syncthreads();
  }

  // ======================= Layer 2: H(128x256) @ W2(256x256) =======================
  {
    #pragma unroll
    for (int mi = 0; mi < 2; mi++)
      for (int nj = 0; nj < 8; nj++)
        for (int q = 0; q < 4; q++) acc[mi][nj][q] = 0.f;

    float4 pw[2];
    auto ldw2 = [&](int kb) {
      #pragma unroll
      for (int i = 0; i < 2; i++) {
        int idx = tid + i * NTHREADS;
        int k = idx >> 6, c4 = idx & 63;
        pw[i] = *reinterpret_cast<const float4*>(W2 + (size_t)(kb + k) * HID + c4 * 4);
      }
    };
    auto stw2 = [&](int buf) {
      #pragma unroll
      for (int i = 0; i < 2; i++) {
        int idx = tid + i * NTHREADS;
        int k = idx >> 6, c4 = idx & 63;
        float4 v = pw[i], o;
        o.x = tfv(v.x); o.y = tfv(v.y); o.z = tfv(v.z); o.w = tfv(v.w);
        *reinterpret_cast<float4*>(Wsm + buf * (KC * WSS) + k * WSS + c4 * 4) = o;
      }
    };

    ldw2(0); stw2(0);
    __syncthreads();
    constexpr int NC2 = HID / KC;   // 16 chunks
    for (int ck = 0; ck < NC2; ck++) {
      if (ck + 1 < NC2) ldw2((ck + 1) * KC);
      const float* As = Hb + (wm * 32) * HS + ck * KC;
      const float* Bs = Wsm + (ck & 1) * (KC * WSS) + wn * 64;
      gemm_chunk<8>(As, HS, Bs, lane, acc);
      if (ck + 1 < NC2) stw2((ck + 1) & 1);
      __syncthreads();
    }
    store_acc(64, 8);
    __syncthreads();
    mix_relu(8, b2);
    __syncthreads();
  }

  // ======================= Layer 3: H(128x256) @ W3(256x128) + pool =======================
  {
    #pragma unroll
    for (int mi = 0; mi < 2; mi++)
      for (int nj = 0; nj < 8; nj++)
        for (int q = 0; q < 4; q++) acc[mi][nj][q] = 0.f;

    float4 pw0;
    auto ldw3 = [&](int kb) {
      int k = tid >> 5, c4 = tid & 31;   // 16 rows x 32 float4s = 512 threads
      pw0 = *reinterpret_cast<const float4*>(W3 + (size_t)(kb + k) * OUTF + c4 * 4);
    };
    auto stw3 = [&](int buf) {
      int k = tid >> 5, c4 = tid & 31;
      float4 v = pw0, o;
      o.x = tfv(v.x); o.y = tfv(v.y); o.z = tfv(v.z); o.w = tfv(v.w);
      *reinterpret_cast<float4*>(Wsm + buf * (KC * WSS) + k * WSS + c4 * 4) = o;
    };

    ldw3(0); stw3(0);
    __syncthreads();
    constexpr int NC3 = HID / KC;   // 16 chunks
    for (int ck = 0; ck < NC3; ck++) {
      if (ck + 1 < NC3) ldw3((ck + 1) * KC);
      const float* As = Hb + (wm * 32) * HS + ck * KC;
      const float* Bs = Wsm + (ck & 1) * (KC * WSS) + wn * 32;
      gemm_chunk<4>(As, HS, Bs, lane, acc);
      if (ck + 1 < NC3) stw3((ck + 1) & 1);
      __syncthreads();
    }
    store_acc(32, 4);
    __syncthreads();

    // Final: lead-mix + b3, then mean/max pool over leads, write (B, 2*OUTF)
    const int ntask = nsamp * OUTF;
    for (int t = tid; t < ntask; t += NTHREADS) {
      int s = t >> 7, cc = t & (OUTF - 1);
      const float* base = Hb + (s * LEADS) * HS + cc;
      float v[12];
      #pragma unroll
      for (int l = 0; l < 12; l++) v[l] = base[l * HS];
      float bv = b3[cc];
      float mean = 0.f;
      float mx = __int_as_float(0xff800000);   // -inf
      #pragma unroll
      for (int n = 0; n < 12; n++) {
        float h = bv;
        #pragma unroll
        for (int m = 0; m < 12; m++) h = fmaf(Am[n * 12 + m], v[m], h);
        mean += h;
        mx = fmaxf(mx, h);
      }
      size_t ob = (size_t)(s0 + s) * (2 * OUTF);
      out[ob + cc] = mean * (1.f / 12.f);
      out[ob + OUTF + cc] = mx;
    }
  }
}

} // anonymous namespace

extern "C" void kernel_launch(void* const* d_in, const int* in_sizes, int n_in,
                              void* d_out, int out_size) {
  const float* x  = (const float*)d_in[0];
  const float* W1 = (const float*)d_in[1];
  const float* b1 = (const float*)d_in[2];
  const float* W2 = (const float*)d_in[3];
  const float* b2 = (const float*)d_in[4];
  const float* W3 = (const float*)d_in[5];
  const float* b3 = (const float*)d_in[6];
  float* out = (float*)d_out;

  cudaFuncSetAttribute(ecg_fused_kernel,
                       cudaFuncAttributeMaxDynamicSharedMemorySize, SMEM_BYTES);

  const int grid = (TOTAL_B + SAMP - 1) / SAMP;   // 1639
  ecg_fused_kernel<<<grid, NTHREADS, SMEM_BYTES>>>(x, W1, b1, W2, b2, W3, b3, out);
}